// round 16
// baseline (speedup 1.0000x reference)
#include <cuda_runtime.h>
#include <cuda_bf16.h>
#include <stdint.h>
#include <math.h>

// ---------------- problem constants ----------------
#define TSTEPS 128
#define BATCH  1024
#define INDIM  47
#define HID    646
#define OUTDIM 5

// ---------------- tiling ----------------
#define MTILE 128
#define NTILE 64
#define KC    64                  // k-chunk (bf16) = 128B row
#define NT    11                  // n-tiles (NPAD 704)
#define MT    8
#define TILES 88                  // per job
#define TPB   544                 // 16 compute warps (4m x 4n, 32x16) + 1 producer
#define NCWARP 16
#define GRID  148

// tiled-block sizes (bytes)
#define A_HALF 16384              // 128 rows x 128B
#define A_BLK  32768              // hi + lo
#define W_HALF 8192               // 64 rows x 128B
#define W_BLK  16384
#define STAGE_B (A_BLK + W_BLK)   // 49152
#define NSTAGE 4
#define SMEM_BYTES (NSTAGE * STAGE_B + 1024)   // 197632

#define SWZ(x) ((x) ^ (((x) >> 3) & 0x70))

// ---------------- device globals (pre-tiled, pre-swizzled; no allocation) ----
#define PSZ ((size_t)MT * NT * A_BLK)
__device__ __align__(1024) char gx[(size_t)TSTEPS * MT * A_BLK];   // 32MB
__device__ __align__(1024) char gh0[2 * PSZ];
__device__ __align__(1024) char gh1[2 * PSZ];
__device__ __align__(1024) char gWih0[NT * 1 * W_BLK];
__device__ __align__(1024) char gWhh0[NT * NT * W_BLK];
__device__ __align__(1024) char gWih1[NT * NT * W_BLK];
__device__ __align__(1024) char gWhh1[NT * NT * W_BLK];
__device__ unsigned int g_counter[TSTEPS + 2];

// ---------------- PTX helpers ----------------
__device__ __forceinline__ uint32_t pkbf(float lo, float hi) {
    uint32_t r;
    asm("cvt.rn.bf16x2.f32 %0, %1, %2;" : "=r"(r) : "f"(hi), "f"(lo));
    return r;
}
__device__ __forceinline__ float fast_tanh(float x) {
    float e = __expf(2.0f * x);
    return 1.0f - __fdividef(2.0f, e + 1.0f);
}
__device__ __forceinline__ void mma_bf16(float* d, const uint32_t a[4], const uint32_t* b) {
    asm volatile(
        "mma.sync.aligned.m16n8k16.row.col.f32.bf16.bf16.f32 "
        "{%0,%1,%2,%3}, {%4,%5,%6,%7}, {%8,%9}, {%0,%1,%2,%3};"
        : "+f"(d[0]), "+f"(d[1]), "+f"(d[2]), "+f"(d[3])
        : "r"(a[0]), "r"(a[1]), "r"(a[2]), "r"(a[3]), "r"(b[0]), "r"(b[1]));
}
#define LDSM_X4(R, addr) \
    asm volatile("ldmatrix.sync.aligned.m8n8.x4.shared.b16 {%0,%1,%2,%3}, [%4];" \
        : "=r"((R)[0]), "=r"((R)[1]), "=r"((R)[2]), "=r"((R)[3]) : "r"(addr))
#define MBARRIER_INIT(addr, cnt) \
    asm volatile("mbarrier.init.shared.b64 [%0], %1;" :: "r"(addr), "r"(cnt) : "memory")
#define MBARRIER_EXPECT_TX(addr, bytes) \
    asm volatile("mbarrier.arrive.expect_tx.shared.b64 _, [%0], %1;" :: "r"(addr), "r"(bytes) : "memory")
#define MBARRIER_ARRIVE(addr) \
    asm volatile("mbarrier.arrive.shared.b64 _, [%0];" :: "r"(addr) : "memory")
#define MBARRIER_WAIT_PARITY(addr, par) do {                                        \
    uint32_t _mb = (addr), _pa = (par), _dn;                                        \
    asm volatile("{ .reg .pred p; mbarrier.try_wait.parity.acquire.cta.shared::cta.b64 p, [%1], %2; selp.b32 %0, 1, 0, p; }" \
        : "=r"(_dn) : "r"(_mb), "r"(_pa) : "memory");                               \
    if (!_dn) {                                                                     \
        asm volatile("{ .reg .pred P1; WL%=: mbarrier.try_wait.parity.acquire.cta.shared::cta.b64 P1, [%0], %1, 0x989680; @P1 bra.uni WD%=; bra.uni WL%=; WD%=: }" \
            :: "r"(_mb), "r"(_pa) : "memory");                                      \
    }                                                                               \
} while (0)
#define BULK_G2S(dst, src, bytes, mbar) \
    asm volatile("cp.async.bulk.shared::cluster.global.mbarrier::complete_tx::bytes [%0], [%1], %2, [%3];" \
        :: "r"(dst), "l"(src), "r"(bytes), "r"(mbar) : "memory")

// ---------------- preprocessing: split to bf16 hi/lo, tiled + SW128 layout ----
__device__ __forceinline__ void store_split(char* base, uint32_t off, float v, int half_b) {
    __nv_bfloat16 hi = __float2bfloat16(v);
    *(__nv_bfloat16*)(base + off) = hi;
    *(__nv_bfloat16*)(base + half_b + off) = __float2bfloat16(v - __bfloat162float(hi));
}

#define NXE ((long)TSTEPS * MT * 8192)
#define NWHE ((long)NT * NT * 4096)
#define NW0E ((long)NT * 4096)
#define NHZ ((long)2 * PSZ / 16)

__global__ void prep_kernel(const float* __restrict__ xs,
                            const float* __restrict__ Wih0,
                            const float* __restrict__ Whh0,
                            const float* __restrict__ Wih1,
                            const float* __restrict__ Whh1) {
    long i = (long)blockIdx.x * blockDim.x + threadIdx.x;
    if (i < NXE) {
        int bi = (int)(i >> 13), e = (int)(i & 8191);
        int t = bi >> 3, mt = bi & 7, r = e >> 6, k = e & 63;
        float v = (k < INDIM)
            ? xs[((size_t)t * BATCH + mt * 128 + r) * INDIM + k] : 0.0f;
        store_split(gx + (size_t)bi * A_BLK, SWZ(r * 128 + k * 2), v, A_HALF);
    }
    if (i < NWHE) {
        int nt = (int)(i / (NT * 4096)); int rem = (int)(i % (NT * 4096));
        int c = rem >> 12, e = rem & 4095, r = e >> 6, k = e & 63;
        int n = nt * 64 + r, kk = c * 64 + k;
        bool ok = (n < HID) && (kk < HID);
        size_t boff = ((size_t)nt * NT + c) * W_BLK;
        uint32_t soff = SWZ(r * 128 + k * 2);
        store_split(gWhh0 + boff, soff, ok ? Whh0[(size_t)n * HID + kk] : 0.0f, W_HALF);
        store_split(gWih1 + boff, soff, ok ? Wih1[(size_t)n * HID + kk] : 0.0f, W_HALF);
        store_split(gWhh1 + boff, soff, ok ? Whh1[(size_t)n * HID + kk] : 0.0f, W_HALF);
    }
    if (i < NW0E) {
        int nt = (int)(i >> 12), e = (int)(i & 4095), r = e >> 6, k = e & 63;
        int n = nt * 64 + r;
        float v = (n < HID && k < INDIM) ? Wih0[(size_t)n * INDIM + k] : 0.0f;
        store_split(gWih0 + (size_t)nt * W_BLK, SWZ(r * 128 + k * 2), v, W_HALF);
    }
    if (i < NHZ) {
        uint4 z = make_uint4(0, 0, 0, 0);
        ((uint4*)gh0)[i] = z;
        ((uint4*)gh1)[i] = z;
    }
    if (i < TSTEPS + 2) g_counter[i] = 0u;
}

// ---------------- cell kernel ----------------
struct Seg {
    const char* A;   // tiled A blocks: (mt*chunks + c) * A_BLK
    const char* W;   // tiled W blocks: (nt*chunks + c) * W_BLK
    int chunks;
};
struct Job {
    Seg s[2];
    const float *b1, *b2;
    char* C;
};

// producer: wait empty[stage], then expect_tx + 2 bulk copies into stage
__device__ __forceinline__ void issue_at(const Job& jb, int c, int mt, int nt,
                                         uint32_t base, uint32_t full_mb,
                                         uint32_t empty_mb, int g) {
    const int st = g & (NSTAGE - 1);
    const int rnd = g >> 2;
    MBARRIER_WAIT_PARITY(empty_mb + st * 8, (uint32_t)((rnd + 1) & 1));
    const Seg& S = (c < jb.s[0].chunks) ? jb.s[0] : jb.s[1];
    const int cc = (c < jb.s[0].chunks) ? c : c - jb.s[0].chunks;
    const char* Asrc = S.A + ((size_t)mt * S.chunks + cc) * A_BLK;
    const char* Wsrc = S.W + ((size_t)nt * S.chunks + cc) * W_BLK;
    const uint32_t stage = base + st * STAGE_B;
    const uint32_t fmb = full_mb + st * 8;
    MBARRIER_EXPECT_TX(fmb, STAGE_B);
    BULK_G2S(stage, Asrc, A_BLK, fmb);
    BULK_G2S(stage + A_BLK, Wsrc, W_BLK, fmb);
}

// load the 6 LDSM fragments of s-step s into register buffer `buf`
#define LOAD_FRAGS(buf, sb, s) do {                               \
    LDSM_X4(ah[buf][0], (sb) + offA[0][s]);                       \
    LDSM_X4(ah[buf][1], (sb) + offA[1][s]);                       \
    LDSM_X4(al[buf][0], (sb) + offA[0][s] + A_HALF);              \
    LDSM_X4(al[buf][1], (sb) + offA[1][s] + A_HALF);              \
    LDSM_X4(bh[buf], (sb) + offB[s]);                             \
    LDSM_X4(bl[buf], (sb) + offB[s] + W_HALF);                    \
} while (0)

__global__ __launch_bounds__(TPB, 1) void cell_kernel(Job jH, Job jL,
                                                      int cidx, int ntiles) {
    extern __shared__ __align__(1024) char dyn[];
    __shared__ __align__(8) uint64_t s_mbar[2 * NSTAGE];
    __shared__ float s_bias[NTILE];
    __shared__ unsigned int s_idx;

    const int tid = threadIdx.x, lane = tid & 31, wid = tid >> 5;
    const bool is_producer = (wid == NCWARP);
    const int wm0 = (wid & 3) * 32;          // 4 m-warps, 32 rows each
    const int wn0 = ((wid >> 2) & 3) * 16;   // 4 n-warps, 16 cols each
    const int r0 = lane >> 2;
    const int c0 = (lane & 3) * 2;

    uint32_t dyn_u32;
    asm("{ .reg .u64 t; cvta.to.shared.u64 t, %1; cvt.u32.u64 %0, t; }"
        : "=r"(dyn_u32) : "l"(dyn));
    const uint32_t base = (dyn_u32 + 1023) & ~1023u;
    uint32_t mb_u32;
    asm("{ .reg .u64 t; cvta.to.shared.u64 t, %1; cvt.u32.u64 %0, t; }"
        : "=r"(mb_u32) : "l"(&s_mbar[0]));
    const uint32_t full_mb = mb_u32;
    const uint32_t empty_mb = mb_u32 + 8 * NSTAGE;

    if (tid == 0) {
        #pragma unroll
        for (int s = 0; s < NSTAGE; s++) {
            MBARRIER_INIT(full_mb + s * 8, 1);         // tx-based
            MBARRIER_INIT(empty_mb + s * 8, NCWARP);   // one arrive per compute warp
        }
    }
    __syncthreads();

    // ldmatrix within-tile swizzled offsets (compute warps)
    const int lt = lane >> 3, lr = lane & 7;
    uint32_t offA[2][4], offB[4];
    #pragma unroll
    for (int i = 0; i < 2; i++)
        #pragma unroll
        for (int s = 0; s < 4; s++) {
            int rA = wm0 + i * 16 + (lt & 1) * 8 + lr;
            int cb = s * 32 + (lt >> 1) * 16;
            offA[i][s] = SWZ((uint32_t)(rA * 128 + cb));
        }
    // B x4: one load covers both n8 blocks of the 16-wide warp tile:
    // reg order [j0k0, j0k8, j1k0, j1k8]
    #pragma unroll
    for (int s = 0; s < 4; s++) {
        int rB = wn0 + (lt >> 1) * 8 + lr;
        int cb = s * 32 + (lt & 1) * 16;
        offB[s] = SWZ((uint32_t)(rB * 128 + cb)) + A_BLK;
    }

    int gq = 0;    // consumer consumed-chunk cursor
    int gqi = 0;   // producer issued-chunk cursor

    for (;;) {
        if (tid == 0) s_idx = atomicAdd(&g_counter[cidx], 1u);
        __syncthreads();   // s_idx handoff; all warps past prev tile
        const unsigned int idx = s_idx;
        if (idx >= (unsigned int)ntiles) break;

        const Job& jb = (idx < TILES) ? jH : jL;
        const int tile = (idx < TILES) ? (int)idx : (int)idx - TILES;
        const int mt = tile / NT;
        const int nt = tile % NT;
        const int n0 = nt * 64;
        const int nch = jb.s[0].chunks + jb.s[1].chunks;

        if (is_producer) {
            if (lane == 0) {
                for (int c = 0; c < nch; c++) {
                    issue_at(jb, c, mt, nt, base, full_mb, empty_mb, gqi + c);
                }
            }
            gqi += nch;
            continue;   // to tile-top __syncthreads
        }

        // ---- compute warps ----
        if (tid < NTILE) {
            int n = n0 + tid;
            s_bias[tid] = (n < HID) ? (jb.b1[n] + jb.b2[n]) : 0.0f;
        }

        float acc1[2][2][4] = {};
        float acc2[2][2][4] = {};

        for (int c = 0; c < nch; c++) {
            const int st = gq & (NSTAGE - 1);
            const int rnd = gq >> 2;
            MBARRIER_WAIT_PARITY(full_mb + st * 8, (uint32_t)(rnd & 1));

            const uint32_t sb = base + st * STAGE_B;
            uint32_t ah[2][2][4], al[2][2][4], bh[2][4], bl[2][4];
            LOAD_FRAGS(0, sb, 0);
            #pragma unroll
            for (int s = 0; s < 4; s++) {
                const int cur = s & 1;
                if (s < 3) {
                    switch (s + 1) {   // constant buf index for register allocation
                        case 1: LOAD_FRAGS(1, sb, 1); break;
                        case 2: LOAD_FRAGS(0, sb, 2); break;
                        default: LOAD_FRAGS(1, sb, 3); break;
                    }
                }
                // acc1 (4 indep), acc2 term1 (4), acc2 term2 (4; RAW gap = 4 HMMAs)
                #pragma unroll
                for (int i = 0; i < 2; i++)
                    #pragma unroll
                    for (int jj = 0; jj < 2; jj++)
                        mma_bf16(acc1[i][jj], ah[cur][i], &bh[cur][jj * 2]);
                #pragma unroll
                for (int i = 0; i < 2; i++)
                    #pragma unroll
                    for (int jj = 0; jj < 2; jj++)
                        mma_bf16(acc2[i][jj], ah[cur][i], &bl[cur][jj * 2]);
                #pragma unroll
                for (int i = 0; i < 2; i++)
                    #pragma unroll
                    for (int jj = 0; jj < 2; jj++)
                        mma_bf16(acc2[i][jj], al[cur][i], &bh[cur][jj * 2]);
            }
            if (lane == 0) MBARRIER_ARRIVE(empty_mb + st * 8);
            gq++;
        }

        // epilogue: combine, bias + tanh, write h in tiled+swizzled hi/lo layout
        char* cblk = jb.C + ((size_t)mt * NT + nt) * A_BLK;
        #pragma unroll
        for (int i = 0; i < 2; i++) {
            const int grow = wm0 + i * 16 + r0;
            #pragma unroll
            for (int jj = 0; jj < 2; jj++) {
                const int col = wn0 + jj * 8 + c0;
                const float bv0 = s_bias[col], bv1 = s_bias[col + 1];
                const uint32_t o0 = SWZ((uint32_t)(grow * 128 + col * 2));
                const uint32_t o1 = SWZ((uint32_t)((grow + 8) * 128 + col * 2));
                float t00 = fast_tanh(acc1[i][jj][0] + acc2[i][jj][0] + bv0);
                float t01 = fast_tanh(acc1[i][jj][1] + acc2[i][jj][1] + bv1);
                float t10 = fast_tanh(acc1[i][jj][2] + acc2[i][jj][2] + bv0);
                float t11 = fast_tanh(acc1[i][jj][3] + acc2[i][jj][3] + bv1);
                uint32_t u0 = pkbf(t00, t01);
                uint32_t u1 = pkbf(t10, t11);
                *(uint32_t*)(cblk + o0) = u0;
                *(uint32_t*)(cblk + o1) = u1;
                float s00 = t00 - __uint_as_float(u0 << 16);
                float s01 = t01 - __uint_as_float(u0 & 0xFFFF0000u);
                float s10 = t10 - __uint_as_float(u1 << 16);
                float s11 = t11 - __uint_as_float(u1 & 0xFFFF0000u);
                *(uint32_t*)(cblk + A_HALF + o0) = pkbf(s00, s01);
                *(uint32_t*)(cblk + A_HALF + o1) = pkbf(s10, s11);
            }
        }
    }
}

// ---------------- classifier (reads tiled h layout) ----------------
__global__ void classifier_kernel(const char* __restrict__ hbase,
                                  const float* __restrict__ Wout,
                                  const float* __restrict__ bout,
                                  float* __restrict__ out) {
    int warp = (blockIdx.x * blockDim.x + threadIdx.x) >> 5;
    int lane = threadIdx.x & 31;
    if (warp >= BATCH * OUTDIM) return;
    int b = warp / OUTDIM, o = warp % OUTDIM;
    const float* wr = Wout + (size_t)o * HID;
    float s = 0.0f;
    for (int k = lane; k < HID; k += 32) {
        size_t blk = ((size_t)(b >> 7) * NT + (k >> 6)) * A_BLK;
        uint32_t off = SWZ((uint32_t)(((b & 127) * 128) + (k & 63) * 2));
        float hv = __bfloat162float(*(const __nv_bfloat16*)(hbase + blk + off))
                 + __bfloat162float(*(const __nv_bfloat16*)(hbase + blk + A_HALF + off));
        s += hv * wr[k];
    }
    #pragma unroll
    for (int off = 16; off; off >>= 1) s += __shfl_down_sync(0xffffffff, s, off);
    if (lane == 0) out[b * OUTDIM + o] = s + bout[o];
}

// ---------------- host ----------------
extern "C" void kernel_launch(void* const* d_in, const int* in_sizes, int n_in,
                              void* d_out, int out_size) {
    const float* xs   = (const float*)d_in[0];
    const float* Wih0 = (const float*)d_in[1];
    const float* Whh0 = (const float*)d_in[2];
    const float* bih0 = (const float*)d_in[3];
    const float* bhh0 = (const float*)d_in[4];
    const float* Wih1 = (const float*)d_in[5];
    const float* Whh1 = (const float*)d_in[6];
    const float* bih1 = (const float*)d_in[7];
    const float* bhh1 = (const float*)d_in[8];
    const float* Wout = (const float*)d_in[9];
    const float* bout = (const float*)d_in[10];
    float* out = (float*)d_out;

    static int attr_done = 0;
    if (!attr_done) {
        cudaFuncSetAttribute(cell_kernel, cudaFuncAttributeMaxDynamicSharedMemorySize,
                             SMEM_BYTES);
        attr_done = 1;
    }

    void* p;
    char *xb, *h0b, *h1b, *wi0, *wh0, *wi1, *wh1;
    cudaGetSymbolAddress(&p, gx);    xb  = (char*)p;
    cudaGetSymbolAddress(&p, gh0);   h0b = (char*)p;
    cudaGetSymbolAddress(&p, gh1);   h1b = (char*)p;
    cudaGetSymbolAddress(&p, gWih0); wi0 = (char*)p;
    cudaGetSymbolAddress(&p, gWhh0); wh0 = (char*)p;
    cudaGetSymbolAddress(&p, gWih1); wi1 = (char*)p;
    cudaGetSymbolAddress(&p, gWhh1); wh1 = (char*)p;

    prep_kernel<<<(unsigned)((NXE + 255) / 256), 256>>>(xs, Wih0, Whh0, Wih1, Whh1);

    const size_t XB = (size_t)MT * A_BLK;

    // t = 0: layer0 only  (h0(-1) = zeros at parity 1)
    {
        Job j0;
        j0.s[0] = { xb, wi0, 1 };
        j0.s[1] = { h0b + PSZ, wh0, NT };
        j0.b1 = bih0; j0.b2 = bhh0;
        j0.C = h0b;
        cell_kernel<<<GRID, TPB, SMEM_BYTES>>>(j0, j0, 0, TILES);
    }

    // t = 1..127: fused h0(t) || h1(t-1); heavy layer1 job first
    for (int t = 1; t < TSTEPS; t++) {
        const size_t pPrev = (size_t)((t - 1) & 1) * PSZ;
        const size_t pCur  = (size_t)(t & 1) * PSZ;
        Job j1;
        j1.s[0] = { h0b + pPrev, wi1, NT };
        j1.s[1] = { h1b + pCur,  wh1, NT };
        j1.b1 = bih1; j1.b2 = bhh1;
        j1.C = h1b + pPrev;
        Job j0;
        j0.s[0] = { xb + (size_t)t * XB, wi0, 1 };
        j0.s[1] = { h0b + pPrev, wh0, NT };
        j0.b1 = bih0; j0.b2 = bhh0;
        j0.C = h0b + pCur;
        cell_kernel<<<GRID, TPB, SMEM_BYTES>>>(j1, j0, t, 2 * TILES);
    }

    // drain: h1(127)
    {
        Job jf;
        jf.s[0] = { h0b + PSZ, wi1, NT };
        jf.s[1] = { h1b,       wh1, NT };
        jf.b1 = bih1; jf.b2 = bhh1;
        jf.C = h1b + PSZ;
        cell_kernel<<<GRID, TPB, SMEM_BYTES>>>(jf, jf, TSTEPS, TILES);
    }

    classifier_kernel<<<(BATCH * OUTDIM * 32 + 255) / 256, 256>>>(
        h1b + PSZ, Wout, bout, out);
}

// round 17
// speedup vs baseline: 1.0375x; 1.0375x over previous
#include <cuda_runtime.h>
#include <cuda_bf16.h>
#include <stdint.h>
#include <math.h>

// ---------------- problem constants ----------------
#define TSTEPS 128
#define BATCH  1024
#define INDIM  47
#define HID    646
#define OUTDIM 5

// ---------------- tiling ----------------
#define MTILE 128
#define NTILE 64
#define KC    64                  // k-chunk (bf16) = 128B row
#define NT    11                  // n-tiles over 704
#define MT    8
#define TILES 88                  // per job
#define TPB   288                 // 8 compute warps (4m x 2n) + 1 producer
#define NCWARP 8
#define GRID  148

#define HA_CH 21                  // heavy concat k-chunks: [h0 646 | h1 646] -> 1292/64
#define LA_CH 11                  // light concat k-chunks: [h0 646 | x 47]  -> 693/64

// tiled-block sizes (bytes)
#define A_HALF 16384              // 128 rows x 128B
#define A_BLK  32768              // hi + lo
#define W_HALF 8192               // 64 rows x 128B
#define W_BLK  16384
#define STAGE_B (A_BLK + W_BLK)   // 49152
#define NSTAGE 4
#define SMEM_BYTES (NSTAGE * STAGE_B + 1024)   // 197632

#define SWZ(x) ((x) ^ (((x) >> 3) & 0x70))

// ---------------- device globals (pre-tiled, pre-swizzled; no allocation) ----
__device__ __align__(1024) char gx[(size_t)TSTEPS * MT * A_BLK];      // 32MB, x chunks
__device__ __align__(1024) char gHA[2][(size_t)MT * HA_CH * A_BLK];   // heavy concat A
__device__ __align__(1024) char gLA[2][(size_t)MT * LA_CH * A_BLK];   // light concat A
__device__ __align__(1024) char gW1[(size_t)NT * HA_CH * W_BLK];      // [Wih1|Whh1]
__device__ __align__(1024) char gW0[(size_t)NT * LA_CH * W_BLK];      // [Whh0|Wih0]
__device__ unsigned int g_counter[TSTEPS + 2];

// ---------------- PTX helpers ----------------
__device__ __forceinline__ uint32_t pkbf(float lo, float hi) {
    uint32_t r;
    asm("cvt.rn.bf16x2.f32 %0, %1, %2;" : "=r"(r) : "f"(hi), "f"(lo));
    return r;
}
__device__ __forceinline__ float fast_tanh(float x) {
    float e = __expf(2.0f * x);
    return 1.0f - __fdividef(2.0f, e + 1.0f);
}
__device__ __forceinline__ void mma_bf16(float* d, const uint32_t a[4], const uint32_t* b) {
    asm volatile(
        "mma.sync.aligned.m16n8k16.row.col.f32.bf16.bf16.f32 "
        "{%0,%1,%2,%3}, {%4,%5,%6,%7}, {%8,%9}, {%0,%1,%2,%3};"
        : "+f"(d[0]), "+f"(d[1]), "+f"(d[2]), "+f"(d[3])
        : "r"(a[0]), "r"(a[1]), "r"(a[2]), "r"(a[3]), "r"(b[0]), "r"(b[1]));
}
#define LDSM_X4(R, addr) \
    asm volatile("ldmatrix.sync.aligned.m8n8.x4.shared.b16 {%0,%1,%2,%3}, [%4];" \
        : "=r"((R)[0]), "=r"((R)[1]), "=r"((R)[2]), "=r"((R)[3]) : "r"(addr))
#define MBARRIER_INIT(addr, cnt) \
    asm volatile("mbarrier.init.shared.b64 [%0], %1;" :: "r"(addr), "r"(cnt) : "memory")
#define MBARRIER_EXPECT_TX(addr, bytes) \
    asm volatile("mbarrier.arrive.expect_tx.shared.b64 _, [%0], %1;" :: "r"(addr), "r"(bytes) : "memory")
#define MBARRIER_ARRIVE(addr) \
    asm volatile("mbarrier.arrive.shared.b64 _, [%0];" :: "r"(addr) : "memory")
#define MBARRIER_WAIT_PARITY(addr, par) do {                                        \
    uint32_t _mb = (addr), _pa = (par), _dn;                                        \
    asm volatile("{ .reg .pred p; mbarrier.try_wait.parity.acquire.cta.shared::cta.b64 p, [%1], %2; selp.b32 %0, 1, 0, p; }" \
        : "=r"(_dn) : "r"(_mb), "r"(_pa) : "memory");                               \
    if (!_dn) {                                                                     \
        asm volatile("{ .reg .pred P1; WL%=: mbarrier.try_wait.parity.acquire.cta.shared::cta.b64 P1, [%0], %1, 0x989680; @P1 bra.uni WD%=; bra.uni WL%=; WD%=: }" \
            :: "r"(_mb), "r"(_pa) : "memory");                                      \
    }                                                                               \
} while (0)
#define BULK_G2S(dst, src, bytes, mbar) \
    asm volatile("cp.async.bulk.shared::cluster.global.mbarrier::complete_tx::bytes [%0], [%1], %2, [%3];" \
        :: "r"(dst), "l"(src), "r"(bytes), "r"(mbar) : "memory")

// ---------------- preprocessing ----------------
__device__ __forceinline__ void store_split(char* base, uint32_t off, float v, int half_b) {
    __nv_bfloat16 hi = __float2bfloat16(v);
    *(__nv_bfloat16*)(base + off) = hi;
    *(__nv_bfloat16*)(base + half_b + off) = __float2bfloat16(v - __bfloat162float(hi));
}

#define NXE  ((long)TSTEPS * MT * 8192)             // x elements (8.4M) — max range
#define NW1E ((long)NT * HA_CH * 4096)              // 946176
#define NW0E ((long)NT * LA_CH * 4096)              // 495616
#define ZHA  ((long)2 * MT * HA_CH * A_BLK / 16)    // 688128 uint4
#define ZLA  ((long)2 * MT * LA_CH * A_BLK / 16)    // 360448 uint4

__global__ void prep_kernel(const float* __restrict__ xs,
                            const float* __restrict__ Wih0,
                            const float* __restrict__ Whh0,
                            const float* __restrict__ Wih1,
                            const float* __restrict__ Whh1) {
    long i = (long)blockIdx.x * blockDim.x + threadIdx.x;
    if (i < NXE) {   // x chunks: block (t, mt), x at local cols 0-46
        int bi = (int)(i >> 13), e = (int)(i & 8191);
        int t = bi >> 3, mt = bi & 7, r = e >> 6, k = e & 63;
        float v = (k < INDIM)
            ? xs[((size_t)t * BATCH + mt * 128 + r) * INDIM + k] : 0.0f;
        store_split(gx + (size_t)bi * A_BLK, SWZ(r * 128 + k * 2), v, A_HALF);
    }
    if (i < NW1E) {  // W1 = [Wih1 | Whh1] along k
        int nt = (int)(i / (HA_CH * 4096)); int rem = (int)(i % (HA_CH * 4096));
        int c = rem >> 12, e = rem & 4095, r = e >> 6, kl = e & 63;
        int n = nt * 64 + r, k = c * 64 + kl;
        float v = 0.0f;
        if (n < HID) {
            if (k < HID) v = Wih1[(size_t)n * HID + k];
            else if (k < 2 * HID) v = Whh1[(size_t)n * HID + (k - HID)];
        }
        store_split(gW1 + ((size_t)nt * HA_CH + c) * W_BLK, SWZ(r * 128 + kl * 2), v, W_HALF);
    }
    if (i < NW0E) {  // W0 = [Whh0 | Wih0] along k
        int nt = (int)(i / (LA_CH * 4096)); int rem = (int)(i % (LA_CH * 4096));
        int c = rem >> 12, e = rem & 4095, r = e >> 6, kl = e & 63;
        int n = nt * 64 + r, k = c * 64 + kl;
        float v = 0.0f;
        if (n < HID) {
            if (k < HID) v = Whh0[(size_t)n * HID + k];
            else if (k < HID + INDIM) v = Wih0[(size_t)n * INDIM + (k - HID)];
        }
        store_split(gW0 + ((size_t)nt * LA_CH + c) * W_BLK, SWZ(r * 128 + kl * 2), v, W_HALF);
    }
    if (i < ZHA) ((uint4*)gHA)[i] = make_uint4(0, 0, 0, 0);
    if (i < ZLA) ((uint4*)gLA)[i] = make_uint4(0, 0, 0, 0);
    if (i < TSTEPS + 2) g_counter[i] = 0u;
}

// prep2: copy x_0 into gLA[0]'s x-region (cols 646-692 = chunk 10, local 6-52)
__global__ void prep2_kernel() {
    int i = blockIdx.x * blockDim.x + threadIdx.x;
    const int per_mt = 128 * INDIM;
    if (i >= MT * per_mt) return;
    int mt = i / per_mt, e = i % per_mt;
    int r = e / INDIM, j = e % INDIM;
    const char* src = gx + (size_t)mt * A_BLK;                    // t=0 block
    char* dst = gLA[0] + ((size_t)mt * LA_CH + 10) * A_BLK;
    uint32_t so = SWZ((uint32_t)(r * 128 + j * 2));
    uint32_t dO = SWZ((uint32_t)(r * 128 + (6 + j) * 2));
    *(__nv_bfloat16*)(dst + dO) = *(const __nv_bfloat16*)(src + so);
    *(__nv_bfloat16*)(dst + A_HALF + dO) = *(const __nv_bfloat16*)(src + A_HALF + so);
}

// ---------------- cell kernel ----------------
struct Job {
    const char *A, *W;
    int chunks;
    const float *b1, *b2;
    char *C1, *C2;      // output concat buffers (C2 may be null)
    int off1, off2;     // k-column offset of output region (0 or HID)
    int cb1, cb2;       // chunk count (block stride) of dest buffers
};

__device__ __forceinline__ void issue_at(const Job& jb, int c, int mt, int nt,
                                         uint32_t base, uint32_t full_mb,
                                         uint32_t empty_mb, int g) {
    const int st = g & (NSTAGE - 1);
    const int rnd = g >> 2;
    MBARRIER_WAIT_PARITY(empty_mb + st * 8, (uint32_t)((rnd + 1) & 1));
    const char* Asrc = jb.A + ((size_t)mt * jb.chunks + c) * A_BLK;
    const char* Wsrc = jb.W + ((size_t)nt * jb.chunks + c) * W_BLK;
    const uint32_t stage = base + st * STAGE_B;
    const uint32_t fmb = full_mb + st * 8;
    MBARRIER_EXPECT_TX(fmb, STAGE_B);
    BULK_G2S(stage, Asrc, A_BLK, fmb);
    BULK_G2S(stage + A_BLK, Wsrc, W_BLK, fmb);
}

__device__ __forceinline__ void write_h(char* base, int cb, int off, int mt,
                                        int grow, int n,
                                        uint32_t u0, uint32_t u1,
                                        uint32_t l0, uint32_t l1) {
    const int g = off + n;
    char* blk = base + ((size_t)mt * cb + (g >> 6)) * A_BLK;
    const uint32_t o0 = SWZ((uint32_t)(grow * 128 + (g & 63) * 2));
    const uint32_t o1 = SWZ((uint32_t)((grow + 8) * 128 + (g & 63) * 2));
    *(uint32_t*)(blk + o0) = u0;
    *(uint32_t*)(blk + o1) = u1;
    *(uint32_t*)(blk + A_HALF + o0) = l0;
    *(uint32_t*)(blk + A_HALF + o1) = l1;
}

// load the 8 LDSM fragments of s-step s into register buffer `buf`
#define LOAD_FRAGS(buf, sb, s) do {                               \
    LDSM_X4(ah[buf][0], (sb) + offA[0][s]);                       \
    LDSM_X4(ah[buf][1], (sb) + offA[1][s]);                       \
    LDSM_X4(al[buf][0], (sb) + offA[0][s] + A_HALF);              \
    LDSM_X4(al[buf][1], (sb) + offA[1][s] + A_HALF);              \
    LDSM_X4(bh[buf][0], (sb) + offB[0][s]);                       \
    LDSM_X4(bh[buf][1], (sb) + offB[1][s]);                       \
    LDSM_X4(bl[buf][0], (sb) + offB[0][s] + W_HALF);              \
    LDSM_X4(bl[buf][1], (sb) + offB[1][s] + W_HALF);              \
} while (0)

__global__ __launch_bounds__(TPB, 1) void cell_kernel(Job jH, Job jL,
                                                      const char* xsrc, char* xdst,
                                                      int cidx, int nH, int nL, int nX) {
    extern __shared__ __align__(1024) char dyn[];
    __shared__ __align__(8) uint64_t s_mbar[2 * NSTAGE];
    __shared__ float s_bias[NTILE];
    __shared__ unsigned int s_idx;

    const int tid = threadIdx.x, lane = tid & 31, wid = tid >> 5;
    const bool is_producer = (wid == NCWARP);
    const int wm0 = (wid & 3) * 32;          // 4 m-warps
    const int wn0 = ((wid >> 2) & 1) * 32;   // 2 n-warps
    const int r0 = lane >> 2;
    const int c0 = (lane & 3) * 2;
    const int ntiles = nH + nL + nX;

    uint32_t dyn_u32;
    asm("{ .reg .u64 t; cvta.to.shared.u64 t, %1; cvt.u32.u64 %0, t; }"
        : "=r"(dyn_u32) : "l"(dyn));
    const uint32_t base = (dyn_u32 + 1023) & ~1023u;
    uint32_t mb_u32;
    asm("{ .reg .u64 t; cvta.to.shared.u64 t, %1; cvt.u32.u64 %0, t; }"
        : "=r"(mb_u32) : "l"(&s_mbar[0]));
    const uint32_t full_mb = mb_u32;
    const uint32_t empty_mb = mb_u32 + 8 * NSTAGE;

    if (tid == 0) {
        #pragma unroll
        for (int s = 0; s < NSTAGE; s++) {
            MBARRIER_INIT(full_mb + s * 8, 1);
            MBARRIER_INIT(empty_mb + s * 8, NCWARP);
        }
    }
    __syncthreads();

    // ldmatrix within-tile swizzled offsets
    const int lt = lane >> 3, lr = lane & 7;
    uint32_t offA[2][4], offB[2][4];
    #pragma unroll
    for (int i = 0; i < 2; i++)
        #pragma unroll
        for (int s = 0; s < 4; s++) {
            int rA = wm0 + i * 16 + (lt & 1) * 8 + lr;
            int cb = s * 32 + (lt >> 1) * 16;
            offA[i][s] = SWZ((uint32_t)(rA * 128 + cb));
        }
    #pragma unroll
    for (int jp = 0; jp < 2; jp++)
        #pragma unroll
        for (int s = 0; s < 4; s++) {
            int rB = wn0 + jp * 16 + (lt >> 1) * 8 + lr;
            int cb = s * 32 + (lt & 1) * 16;
            offB[jp][s] = SWZ((uint32_t)(rB * 128 + cb)) + A_BLK;
        }

    int gq = 0;    // consumer cursor
    int gqi = 0;   // producer cursor

    for (;;) {
        if (tid == 0) s_idx = atomicAdd(&g_counter[cidx], 1u);
        __syncthreads();
        const unsigned int idx = s_idx;
        if (idx >= (unsigned int)ntiles) break;

        // ---- xcopy tiles: stage x_{t+1} into light buffer tail ----
        if ((int)idx >= nH + nL) {
            const int mt = (int)idx - nH - nL;
            const char* src = xsrc + (size_t)mt * A_BLK;
            char* dst = xdst + ((size_t)mt * LA_CH + 10) * A_BLK;
            for (int e = tid; e < 128 * INDIM; e += TPB) {
                int r = e / INDIM, j = e % INDIM;
                uint32_t so = SWZ((uint32_t)(r * 128 + j * 2));
                uint32_t dO = SWZ((uint32_t)(r * 128 + (6 + j) * 2));
                *(__nv_bfloat16*)(dst + dO) = *(const __nv_bfloat16*)(src + so);
                *(__nv_bfloat16*)(dst + A_HALF + dO) = *(const __nv_bfloat16*)(src + A_HALF + so);
            }
            continue;
        }

        const bool heavy = ((int)idx < nH);
        const Job& jb = heavy ? jH : jL;
        const int tile = heavy ? (int)idx : (int)idx - nH;
        const int mt = tile / NT;
        const int nt = tile % NT;
        const int n0 = nt * 64;
        const int nch = jb.chunks;

        if (is_producer) {
            if (lane == 0) {
                for (int c = 0; c < nch; c++)
                    issue_at(jb, c, mt, nt, base, full_mb, empty_mb, gqi + c);
            }
            gqi += nch;
            continue;
        }

        // ---- compute warps ----
        if (tid < NTILE) {
            int n = n0 + tid;
            s_bias[tid] = (n < HID) ? (jb.b1[n] + jb.b2[n]) : 0.0f;
        }

        float acc1[2][4][4] = {};
        float acc2[2][4][4] = {};

        for (int c = 0; c < nch; c++) {
            const int st = gq & (NSTAGE - 1);
            const int rnd = gq >> 2;
            MBARRIER_WAIT_PARITY(full_mb + st * 8, (uint32_t)(rnd & 1));

            const uint32_t sb = base + st * STAGE_B;
            uint32_t ah[2][2][4], al[2][2][4], bh[2][2][4], bl[2][2][4];
            LOAD_FRAGS(0, sb, 0);
            #pragma unroll
            for (int s = 0; s < 4; s++) {
                const int cur = s & 1;
                if (s < 3) {
                    switch (s + 1) {
                        case 1: LOAD_FRAGS(1, sb, 1); break;
                        case 2: LOAD_FRAGS(0, sb, 2); break;
                        default: LOAD_FRAGS(1, sb, 3); break;
                    }
                }
                #pragma unroll
                for (int i = 0; i < 2; i++)
                    #pragma unroll
                    for (int jj = 0; jj < 4; jj++)
                        mma_bf16(acc1[i][jj], ah[cur][i], &bh[cur][jj >> 1][(jj & 1) * 2]);
                #pragma unroll
                for (int i = 0; i < 2; i++)
                    #pragma unroll
                    for (int jj = 0; jj < 4; jj++)
                        mma_bf16(acc2[i][jj], ah[cur][i], &bl[cur][jj >> 1][(jj & 1) * 2]);
                #pragma unroll
                for (int i = 0; i < 2; i++)
                    #pragma unroll
                    for (int jj = 0; jj < 4; jj++)
                        mma_bf16(acc2[i][jj], al[cur][i], &bh[cur][jj >> 1][(jj & 1) * 2]);
            }
            if (lane == 0) MBARRIER_ARRIVE(empty_mb + st * 8);
            gq++;
        }

        // epilogue: combine, bias + tanh, write into next-parity concat buffers
        #pragma unroll
        for (int i = 0; i < 2; i++) {
            const int grow = wm0 + i * 16 + r0;
            #pragma unroll
            for (int jj = 0; jj < 4; jj++) {
                const int col = wn0 + jj * 8 + c0;
                const int n = n0 + col;
                if (n >= HID) continue;          // n even, HID even -> pair valid
                const float bv0 = s_bias[col], bv1 = s_bias[col + 1];
                float t00 = fast_tanh(acc1[i][jj][0] + acc2[i][jj][0] + bv0);
                float t01 = fast_tanh(acc1[i][jj][1] + acc2[i][jj][1] + bv1);
                float t10 = fast_tanh(acc1[i][jj][2] + acc2[i][jj][2] + bv0);
                float t11 = fast_tanh(acc1[i][jj][3] + acc2[i][jj][3] + bv1);
                uint32_t u0 = pkbf(t00, t01);
                uint32_t u1 = pkbf(t10, t11);
                float s00 = t00 - __uint_as_float(u0 << 16);
                float s01 = t01 - __uint_as_float(u0 & 0xFFFF0000u);
                float s10 = t10 - __uint_as_float(u1 << 16);
                float s11 = t11 - __uint_as_float(u1 & 0xFFFF0000u);
                uint32_t l0 = pkbf(s00, s01);
                uint32_t l1 = pkbf(s10, s11);
                write_h(jb.C1, jb.cb1, jb.off1, mt, grow, n, u0, u1, l0, l1);
                if (jb.C2)
                    write_h(jb.C2, jb.cb2, jb.off2, mt, grow, n, u0, u1, l0, l1);
            }
        }
    }
}

// ---------------- classifier (reads h1 region of heavy concat buffer) ------
__global__ void classifier_kernel(const char* __restrict__ hbase,
                                  const float* __restrict__ Wout,
                                  const float* __restrict__ bout,
                                  float* __restrict__ out) {
    int warp = (blockIdx.x * blockDim.x + threadIdx.x) >> 5;
    int lane = threadIdx.x & 31;
    if (warp >= BATCH * OUTDIM) return;
    int b = warp / OUTDIM, o = warp % OUTDIM;
    const float* wr = Wout + (size_t)o * HID;
    float s = 0.0f;
    for (int k = lane; k < HID; k += 32) {
        int g = HID + k;     // h1 region
        size_t blk = ((size_t)(b >> 7) * HA_CH + (g >> 6)) * A_BLK;
        uint32_t off = SWZ((uint32_t)(((b & 127) * 128) + (g & 63) * 2));
        float hv = __bfloat162float(*(const __nv_bfloat16*)(hbase + blk + off))
                 + __bfloat162float(*(const __nv_bfloat16*)(hbase + blk + A_HALF + off));
        s += hv * wr[k];
    }
    #pragma unroll
    for (int off = 16; off; off >>= 1) s += __shfl_down_sync(0xffffffff, s, off);
    if (lane == 0) out[b * OUTDIM + o] = s + bout[o];
}

// ---------------- host ----------------
extern "C" void kernel_launch(void* const* d_in, const int* in_sizes, int n_in,
                              void* d_out, int out_size) {
    const float* xs   = (const float*)d_in[0];
    const float* Wih0 = (const float*)d_in[1];
    const float* Whh0 = (const float*)d_in[2];
    const float* bih0 = (const float*)d_in[3];
    const float* bhh0 = (const float*)d_in[4];
    const float* Wih1 = (const float*)d_in[5];
    const float* Whh1 = (const float*)d_in[6];
    const float* bih1 = (const float*)d_in[7];
    const float* bhh1 = (const float*)d_in[8];
    const float* Wout = (const float*)d_in[9];
    const float* bout = (const float*)d_in[10];
    float* out = (float*)d_out;

    static int attr_done = 0;
    if (!attr_done) {
        cudaFuncSetAttribute(cell_kernel, cudaFuncAttributeMaxDynamicSharedMemorySize,
                             SMEM_BYTES);
        attr_done = 1;
    }

    void* p;
    char *xb, *ha0, *ha1, *la0, *la1, *w1, *w0;
    cudaGetSymbolAddress(&p, gx);  xb = (char*)p;
    cudaGetSymbolAddress(&p, gHA); ha0 = (char*)p; ha1 = ha0 + (size_t)MT * HA_CH * A_BLK;
    cudaGetSymbolAddress(&p, gLA); la0 = (char*)p; la1 = la0 + (size_t)MT * LA_CH * A_BLK;
    cudaGetSymbolAddress(&p, gW1); w1 = (char*)p;
    cudaGetSymbolAddress(&p, gW0); w0 = (char*)p;
    char* haP[2] = { ha0, ha1 };
    char* laP[2] = { la0, la1 };

    prep_kernel<<<(unsigned)((NXE + 255) / 256), 256>>>(xs, Wih0, Whh0, Wih1, Whh1);
    prep2_kernel<<<(MT * 128 * INDIM + 255) / 256, 256>>>();

    const size_t XB = (size_t)MT * A_BLK;   // per-timestep x stride

    // t = 0: light only (h0(0) from [h0(-1)=0 | x_0]); xcopy stages x_1
    {
        Job jl;
        jl.A = laP[0]; jl.W = w0; jl.chunks = LA_CH;
        jl.b1 = bih0; jl.b2 = bhh0;
        jl.C1 = laP[1]; jl.off1 = 0; jl.cb1 = LA_CH;
        jl.C2 = haP[1]; jl.off2 = 0; jl.cb2 = HA_CH;
        cell_kernel<<<GRID, TPB, SMEM_BYTES>>>(jl, jl, xb + XB, laP[1], 0,
                                               0, TILES, MT);
    }

    // t = 1..127: heavy (h1(t-1)) + light (h0(t)) + xcopy (x_{t+1})
    for (int t = 1; t < TSTEPS; t++) {
        const int b = t & 1, nb = b ^ 1;
        Job jh;
        jh.A = haP[b]; jh.W = w1; jh.chunks = HA_CH;
        jh.b1 = bih1; jh.b2 = bhh1;
        jh.C1 = haP[nb]; jh.off1 = HID; jh.cb1 = HA_CH;
        jh.C2 = nullptr; jh.off2 = 0; jh.cb2 = 0;
        Job jl;
        jl.A = laP[b]; jl.W = w0; jl.chunks = LA_CH;
        jl.b1 = bih0; jl.b2 = bhh0;
        jl.C1 = laP[nb]; jl.off1 = 0; jl.cb1 = LA_CH;
        jl.C2 = haP[nb]; jl.off2 = 0; jl.cb2 = HA_CH;
        const int nX = (t < TSTEPS - 1) ? MT : 0;
        const char* xsrc = (t < TSTEPS - 1) ? (xb + (size_t)(t + 1) * XB) : nullptr;
        cell_kernel<<<GRID, TPB, SMEM_BYTES>>>(jh, jl, xsrc, laP[nb], t,
                                               TILES, TILES, nX);
    }

    // drain: h1(127) = g(h0(127), h1(126)) from heavyA[0] -> heavyA[1].h1
    {
        Job jf;
        jf.A = haP[0]; jf.W = w1; jf.chunks = HA_CH;
        jf.b1 = bih1; jf.b2 = bhh1;
        jf.C1 = haP[1]; jf.off1 = HID; jf.cb1 = HA_CH;
        jf.C2 = nullptr; jf.off2 = 0; jf.cb2 = 0;
        cell_kernel<<<GRID, TPB, SMEM_BYTES>>>(jf, jf, nullptr, nullptr, TSTEPS,
                                               TILES, 0, 0);
    }

    classifier_kernel<<<(BATCH * OUTDIM * 32 + 255) / 256, 256>>>(
        haP[1], Wout, bout, out);
}